// round 15
// baseline (speedup 1.0000x reference)
#include <cuda_runtime.h>
#include <math.h>
#include <stdint.h>

// Scratch (device globals -- no runtime allocation allowed)
__device__ float g_X0[2048 * 1024];   // enc layer0 input gates  [s*32+b][j]
__device__ float g_Xd[3200 * 1024];   // dec input gates         [t*32+b][j]
__device__ float g_enc[32 * 64 * 256];// enc_out [b][s][h]
__device__ float g_htop[32 * 256];    // final top-layer h
__device__ float g_H2[3200 * 256];    // decoder hiddens [b*100+t][h]
// transposed weights [k][j] for broadcast-FMA GEMVs
__device__ float g_WT0[256 * 1024];   // Whh0^T
__device__ float g_WT1[512 * 1024];   // [Wih1 ; Whh1]^T
__device__ float g_WTd[512 * 1024];   // [dWih[:,128:384] ; dWhh]^T

__device__ __forceinline__ float sigf(float x) { return 1.f / (1.f + expf(-x)); }

__device__ __forceinline__ float wred(float v) {
#pragma unroll
    for (int o = 16; o; o >>= 1) v += __shfl_xor_sync(0xffffffffu, v, o);
    return v;
}

// DSMEM store: write v to the same smem offset in cluster CTA `rank`
__device__ __forceinline__ void stc(float* p, int rank, float v) {
    unsigned a = (unsigned)__cvta_generic_to_shared(p);
    unsigned r;
    asm volatile("mapa.shared::cluster.u32 %0, %1, %2;" : "=r"(r) : "r"(a), "r"(rank));
    asm volatile("st.shared::cluster.f32 [%0], %1;" :: "r"(r), "f"(v) : "memory");
}
__device__ __forceinline__ void csync() {
    asm volatile("barrier.cluster.arrive.aligned;" ::: "memory");
    asm volatile("barrier.cluster.wait.aligned;" ::: "memory");
}

// packed f32x2 FMA (sm_100+ PTX)
__device__ __forceinline__ unsigned long long pk2(float lo, float hi) {
    unsigned long long r;
    asm("mov.b64 %0, {%1,%2};" : "=l"(r) : "f"(lo), "f"(hi));
    return r;
}
__device__ __forceinline__ void fma2(unsigned long long& d, unsigned long long a,
                                     unsigned long long b) {
    asm("fma.rn.f32x2 %0, %1, %2, %0;" : "+l"(d) : "l"(a), "l"(b));
}
__device__ __forceinline__ void upk2(unsigned long long v, float& lo, float& hi) {
    asm("mov.b64 {%0,%1}, %2;" : "=f"(lo), "=f"(hi) : "l"(v));
}

// ============================================================================
// k_tr: transpose recurrent weights into [k][j] layout (1280 rows of 1024)
// ============================================================================
__global__ void k_tr(const float* __restrict__ Whh0, const float* __restrict__ Wih1,
                     const float* __restrict__ Whh1, const float* __restrict__ dWih,
                     const float* __restrict__ dWhh)
{
    const int row = blockIdx.x;
    const int j0 = threadIdx.x * 4;
    const float* src; long stride; float* dst; int k;
    if (row < 256) {
        k = row; src = Whh0 + k; stride = 256; dst = g_WT0 + k * 1024;
    } else if (row < 768) {
        k = row - 256;
        src = (k < 256) ? (Wih1 + k) : (Whh1 + (k - 256));
        stride = 256; dst = g_WT1 + k * 1024;
    } else {
        k = row - 768;
        if (k < 256) { src = dWih + 128 + k; stride = 384; }
        else         { src = dWhh + (k - 256); stride = 256; }
        dst = g_WTd + k * 1024;
    }
    float4 v;
    v.x = __ldg(src + (long)(j0 + 0) * stride);
    v.y = __ldg(src + (long)(j0 + 1) * stride);
    v.z = __ldg(src + (long)(j0 + 2) * stride);
    v.w = __ldg(src + (long)(j0 + 3) * stride);
    *(float4*)(dst + j0) = v;
}

// ============================================================================
// k_pre: X0[r][j] = b0[j] + emb(q)[r].Wih0[j]; Xd[r][j] = db[j] + emb(d)[r].dWih[j][0:128]
// ============================================================================
__global__ void k_pre(const int* __restrict__ qids, const int* __restrict__ sids,
                      const float* __restrict__ encE, const float* __restrict__ Wih0,
                      const float* __restrict__ b0, const float* __restrict__ decE,
                      const float* __restrict__ dWih, const float* __restrict__ db)
{
    __shared__ __align__(16) float4 a_s[16 * 32];
    const int blk = blockIdx.x, tid = threadIdx.x;
    const bool isX0 = blk < 512;
    const int u = isX0 ? blk : blk - 512;
    const int rt = u >> 2, jb = (u & 3) << 8;
    const float4* Ef = (const float4*)(isX0 ? encE : decE);
#pragma unroll
    for (int i = 0; i < 2; ++i) {
        int lin = tid + i * 256;
        int rr = lin >> 5, e4 = lin & 31;
        int row = rt * 16 + rr, b = row & 31, idx = row >> 5;
        int tok = isX0 ? qids[b * 64 + idx] : (idx == 0 ? 1 : sids[b * 100 + idx - 1]);
        a_s[rr * 32 + e4] = Ef[(size_t)tok * 32 + e4];
    }
    __syncthreads();
    const int j = jb + tid;
    const float4* Wf = (const float4*)(isX0 ? (Wih0 + j * 128) : (dWih + j * 384));
    float acc[16];
#pragma unroll
    for (int r = 0; r < 16; ++r) acc[r] = 0.f;
#pragma unroll 4
    for (int e4 = 0; e4 < 32; ++e4) {
        float4 w = __ldg(Wf + e4);
#pragma unroll
        for (int r = 0; r < 16; ++r) {
            float4 a = a_s[r * 32 + e4];
            acc[r] += a.x * w.x + a.y * w.y + a.z * w.z + a.w * w.w;
        }
    }
    const float bias = isX0 ? __ldg(b0 + j) : __ldg(db + j);
    float* dst = isX0 ? g_X0 : g_Xd;
#pragma unroll
    for (int r = 0; r < 16; ++r) dst[(rt * 16 + r) * 1024 + j] = bias + acc[r];
}

// ============================================================================
// Cluster-8 recurrence (R10 proven): 2 batch elems per cluster in f32x2 lanes;
// rank owns 32 hidden units.  k_enc unchanged from the 2494us winner.
// ============================================================================
__global__ void __launch_bounds__(512) __cluster_dims__(8, 1, 1)
k_enc(const float* __restrict__ b1)
{
    __shared__ __align__(16) float2 H0[2][256], H1[2][256];
    __shared__ __align__(16) float2 part[16][128];
    __shared__ __align__(16) float2 gt[128];
    const int cid = blockIdx.x >> 3, rank = blockIdx.x & 7;
    const int b0 = 2 * cid;
    const int tid = threadIdx.x;
    const int q = tid >> 5, cg = tid & 31;
    const int colf4 = (cg >> 3) * 64 + 8 * rank + (cg & 7);
    const int jg = (tid >> 5) * 256 + 32 * rank + (tid & 31);   // valid tid<128
    float c0 = 0.f, c1 = 0.f;
    float bias1 = (tid < 128) ? __ldg(b1 + jg) : 0.f;

    if (tid < 256) { H0[0][tid] = make_float2(0.f, 0.f); H1[0][tid] = make_float2(0.f, 0.f); }
    __syncthreads();

    for (int s = 0; s < 64; ++s) {
        const int p = s & 1;
        float xa = 0.f, xb = 0.f;
        if (tid < 128) {
            xa = __ldg(&g_X0[(s * 32 + b0) * 1024 + jg]);
            xb = __ldg(&g_X0[(s * 32 + b0 + 1) * 1024 + jg]);
        }
        // ---- L0 gates: K=256, 16 k per slice ----
        {
            const unsigned long long* hv = (const unsigned long long*)&H0[p][16 * q];
            const float4* wp = (const float4*)g_WT0 + (16 * q) * 256 + colf4;
            unsigned long long a0 = 0, a1 = 0, a2 = 0, a3 = 0;
#pragma unroll
            for (int k = 0; k < 16; ++k) {
                unsigned long long hp = hv[k];
                float4 w = __ldg(wp); wp += 256;
                fma2(a0, hp, pk2(w.x, w.x));
                fma2(a1, hp, pk2(w.y, w.y));
                fma2(a2, hp, pk2(w.z, w.z));
                fma2(a3, hp, pk2(w.w, w.w));
            }
            unsigned long long* pr = (unsigned long long*)&part[q][cg * 4];
            pr[0] = a0; pr[1] = a1; pr[2] = a2; pr[3] = a3;
        }
        __syncthreads();
        if (tid < 128) {
            float sx = xa, sy = xb;
#pragma unroll
            for (int qq = 0; qq < 16; ++qq) { float2 v = part[qq][tid]; sx += v.x; sy += v.y; }
            gt[tid] = make_float2(sx, sy);
        }
        __syncthreads();
        if (tid < 64) {
            int bh = tid >> 5, un = tid & 31;
            float gi_ = bh ? gt[un].y : gt[un].x;
            float gf_ = bh ? gt[32 + un].y : gt[32 + un].x;
            float gg_ = bh ? gt[64 + un].y : gt[64 + un].x;
            float go_ = bh ? gt[96 + un].y : gt[96 + un].x;
            c0 = sigf(gf_) * c0 + sigf(gi_) * tanhf(gg_);
            float hn = sigf(go_) * tanhf(c0);
            float* dst = ((float*)&H0[p ^ 1][32 * rank + un]) + bh;
#pragma unroll
            for (int r = 0; r < 8; ++r) stc(dst, r, hn);
        }
        csync();
        // ---- L1 gates: K=512 = [H0_new ; H1_prev], 32 k per slice ----
        {
            const unsigned long long* hv = (q < 8)
                ? (const unsigned long long*)&H0[p ^ 1][32 * q]
                : (const unsigned long long*)&H1[p][32 * (q - 8)];
            const float4* wp = (const float4*)g_WT1 + (32 * q) * 256 + colf4;
            unsigned long long a0 = 0, a1 = 0, a2 = 0, a3 = 0;
#pragma unroll
            for (int k = 0; k < 32; ++k) {
                unsigned long long hp = hv[k];
                float4 w = __ldg(wp); wp += 256;
                fma2(a0, hp, pk2(w.x, w.x));
                fma2(a1, hp, pk2(w.y, w.y));
                fma2(a2, hp, pk2(w.z, w.z));
                fma2(a3, hp, pk2(w.w, w.w));
            }
            unsigned long long* pr = (unsigned long long*)&part[q][cg * 4];
            pr[0] = a0; pr[1] = a1; pr[2] = a2; pr[3] = a3;
        }
        __syncthreads();
        if (tid < 128) {
            float sx = bias1, sy = bias1;
#pragma unroll
            for (int qq = 0; qq < 16; ++qq) { float2 v = part[qq][tid]; sx += v.x; sy += v.y; }
            gt[tid] = make_float2(sx, sy);
        }
        __syncthreads();
        if (tid < 64) {
            int bh = tid >> 5, un = tid & 31;
            float gi_ = bh ? gt[un].y : gt[un].x;
            float gf_ = bh ? gt[32 + un].y : gt[32 + un].x;
            float gg_ = bh ? gt[64 + un].y : gt[64 + un].x;
            float go_ = bh ? gt[96 + un].y : gt[96 + un].x;
            c1 = sigf(gf_) * c1 + sigf(gi_) * tanhf(gg_);
            float hn = sigf(go_) * tanhf(c1);
            float* dst = ((float*)&H1[p ^ 1][32 * rank + un]) + bh;
#pragma unroll
            for (int r = 0; r < 8; ++r) stc(dst, r, hn);
            g_enc[((b0 + bh) * 64 + s) * 256 + 32 * rank + un] = hn;
            if (s == 63) g_htop[(b0 + bh) * 256 + 32 * rank + un] = hn;
        }
        csync();
    }
}

// ============================================================================
// k_dec: ONE csync per step.  Attention (scores, softmax, ctx) is fully
// replicated per CTA (enc is read-only, L2-resident) -> no cross-CTA sharing
// needed until the h broadcast after the cell.
// ============================================================================
__global__ void __launch_bounds__(512) __cluster_dims__(8, 1, 1)
k_dec()
{
    __shared__ __align__(16) float2 Hd[2][256], Ctx[256];
    __shared__ __align__(16) float2 part[16][128];
    __shared__ __align__(16) float2 gt[128];
    __shared__ float sc[2][64];
    __shared__ float rz[2];
    const int cid = blockIdx.x >> 3, rank = blockIdx.x & 7;
    const int b0 = 2 * cid;
    const int tid = threadIdx.x;
    const int q = tid >> 5, cg = tid & 31;
    const int colf4 = (cg >> 3) * 64 + 8 * rank + (cg & 7);
    const int jg = (tid >> 5) * 256 + 32 * rank + (tid & 31);

    if (tid < 256)
        Hd[0][tid] = make_float2(g_htop[b0 * 256 + tid], g_htop[(b0 + 1) * 256 + tid]);
    __syncthreads();

    for (int t = 0; t < 100; ++t) {
        const int p = t & 1;
        float xa = 0.f, xb = 0.f;
        if (tid < 128) {
            xa = __ldg(&g_Xd[(t * 32 + b0) * 1024 + jg]);
            xb = __ldg(&g_Xd[(t * 32 + b0 + 1) * 1024 + jg]);
        }
        // ---- scores (replicated): bh = tid>>8, s = (tid&255)>>2, qq = tid&3 ----
        {
            int bh = tid >> 8, rest = tid & 255;
            int s = rest >> 2, qq = rest & 3;
            const float4* er = (const float4*)(g_enc + ((b0 + bh) * 64 + s) * 256 + qq * 64);
            const float2* hp = &Hd[p][qq * 64];
            float pr = 0.f;
#pragma unroll
            for (int i = 0; i < 16; ++i) {
                float4 e4 = __ldg(er + i);
                float2 h0p = hp[i * 4 + 0], h1p = hp[i * 4 + 1];
                float2 h2p = hp[i * 4 + 2], h3p = hp[i * 4 + 3];
                float hv0 = bh ? h0p.y : h0p.x;
                float hv1 = bh ? h1p.y : h1p.x;
                float hv2 = bh ? h2p.y : h2p.x;
                float hv3 = bh ? h3p.y : h3p.x;
                pr += e4.x * hv0 + e4.y * hv1 + e4.z * hv2 + e4.w * hv3;
            }
            pr += __shfl_xor_sync(0xffffffffu, pr, 1);
            pr += __shfl_xor_sync(0xffffffffu, pr, 2);
            if (qq == 0) sc[bh][s] = pr;
        }
        __syncthreads();
        // ---- softmax (local) ----
        if (tid < 64) {
            int bh = tid >> 5, l = tid & 31;
            float s0 = sc[bh][l], s1 = sc[bh][l + 32];
            float m = fmaxf(s0, s1);
#pragma unroll
            for (int o = 16; o; o >>= 1) m = fmaxf(m, __shfl_xor_sync(0xffffffffu, m, o));
            float e0 = expf(s0 - m), e1 = expf(s1 - m);
            sc[bh][l] = e0; sc[bh][l + 32] = e1;
            float ssum = wred(e0 + e1);
            if (l == 0) rz[bh] = 1.f / ssum;
        }
        __syncthreads();
        // ---- ctx (replicated): bh = tid>>8, k = tid&255 ----
        {
            int bh = tid >> 8, k = tid & 255;
            const float* base = g_enc + (b0 + bh) * 64 * 256 + k;
            float a = 0.f;
#pragma unroll 8
            for (int s = 0; s < 64; ++s) a += sc[bh][s] * __ldg(base + s * 256);
            ((float*)&Ctx[k])[bh] = a * rz[bh];
        }
        __syncthreads();
        // ---- gates: K=512 = [Ctx ; Hd[p]], 32 k per slice ----
        {
            const unsigned long long* hv = (q < 8)
                ? (const unsigned long long*)&Ctx[32 * q]
                : (const unsigned long long*)&Hd[p][32 * (q - 8)];
            const float4* wp = (const float4*)g_WTd + (32 * q) * 256 + colf4;
            unsigned long long a0 = 0, a1 = 0, a2 = 0, a3 = 0;
#pragma unroll
            for (int k = 0; k < 32; ++k) {
                unsigned long long hp = hv[k];
                float4 w = __ldg(wp); wp += 256;
                fma2(a0, hp, pk2(w.x, w.x));
                fma2(a1, hp, pk2(w.y, w.y));
                fma2(a2, hp, pk2(w.z, w.z));
                fma2(a3, hp, pk2(w.w, w.w));
            }
            unsigned long long* pr = (unsigned long long*)&part[q][cg * 4];
            pr[0] = a0; pr[1] = a1; pr[2] = a2; pr[3] = a3;
        }
        __syncthreads();
        if (tid < 128) {
            float sx = xa, sy = xb;
#pragma unroll
            for (int qq = 0; qq < 16; ++qq) { float2 v = part[qq][tid]; sx += v.x; sy += v.y; }
            gt[tid] = make_float2(sx, sy);
        }
        __syncthreads();
        // ---- cell (c_in = 0): h2 = sig(o)*tanh(sig(i)*tanh(g)) ----
        if (tid < 64) {
            int bh = tid >> 5, un = tid & 31;
            float gi_ = bh ? gt[un].y : gt[un].x;
            float gg_ = bh ? gt[64 + un].y : gt[64 + un].x;
            float go_ = bh ? gt[96 + un].y : gt[96 + un].x;
            float h2 = sigf(go_) * tanhf(sigf(gi_) * tanhf(gg_));
            float* dst = ((float*)&Hd[p ^ 1][32 * rank + un]) + bh;
#pragma unroll
            for (int r = 0; r < 8; ++r) stc(dst, r, h2);
            g_H2[((b0 + bh) * 100 + t) * 256 + 32 * rank + un] = h2;
        }
        csync();   // single per-step cluster barrier (h broadcast)
    }
}

// ============================================================================
// k_out: out[r][v] = H2[r].Wout[v] + bout[v]; 128x128x16 tiles, FFMA2 (proven)
// ============================================================================
__global__ void __launch_bounds__(256) k_out(const float* __restrict__ Wout,
                                             const float* __restrict__ bout,
                                             float* __restrict__ out)
{
    __shared__ __align__(16) float As[16][132], Bs[16][132];
    const int tid = threadIdx.x;
    const int rb = blockIdx.y * 128, vb = blockIdx.x * 128;
    const int tx = tid & 15, ty = tid >> 4;
    const int r0 = tid >> 2, k0 = (tid & 3) * 4;
    const int r1 = (tid + 256) >> 2, k1 = ((tid + 256) & 3) * 4;

    unsigned long long acc[8][4];
#pragma unroll
    for (int i = 0; i < 8; ++i)
#pragma unroll
        for (int j = 0; j < 4; ++j) acc[i][j] = 0ull;

    const float* A = g_H2;
    float4 a0 = *(const float4*)(A + (rb + r0) * 256 + k0);
    float4 a1 = *(const float4*)(A + (rb + r1) * 256 + k1);
    float4 bv0 = *(const float4*)(Wout + (size_t)(vb + r0) * 256 + k0);
    float4 bv1 = *(const float4*)(Wout + (size_t)(vb + r1) * 256 + k1);

    for (int kc = 0; kc < 16; ++kc) {
        As[k0 + 0][r0] = a0.x; As[k0 + 1][r0] = a0.y; As[k0 + 2][r0] = a0.z; As[k0 + 3][r0] = a0.w;
        As[k1 + 0][r1] = a1.x; As[k1 + 1][r1] = a1.y; As[k1 + 2][r1] = a1.z; As[k1 + 3][r1] = a1.w;
        Bs[k0 + 0][r0] = bv0.x; Bs[k0 + 1][r0] = bv0.y; Bs[k0 + 2][r0] = bv0.z; Bs[k0 + 3][r0] = bv0.w;
        Bs[k1 + 0][r1] = bv1.x; Bs[k1 + 1][r1] = bv1.y; Bs[k1 + 2][r1] = bv1.z; Bs[k1 + 3][r1] = bv1.w;
        __syncthreads();
        if (kc < 15) {
            int kb = (kc + 1) * 16;
            a0 = *(const float4*)(A + (rb + r0) * 256 + kb + k0);
            a1 = *(const float4*)(A + (rb + r1) * 256 + kb + k1);
            bv0 = *(const float4*)(Wout + (size_t)(vb + r0) * 256 + kb + k0);
            bv1 = *(const float4*)(Wout + (size_t)(vb + r1) * 256 + kb + k1);
        }
#pragma unroll
        for (int k = 0; k < 16; ++k) {
            float4 aA = *(const float4*)&As[k][ty * 4];
            float4 aB = *(const float4*)&As[k][ty * 4 + 64];
            float4 bA = *(const float4*)&Bs[k][tx * 4];
            float4 bB = *(const float4*)&Bs[k][tx * 4 + 64];
            unsigned long long bp[4] = { pk2(bA.x, bA.y), pk2(bA.z, bA.w),
                                         pk2(bB.x, bB.y), pk2(bB.z, bB.w) };
            float av[8] = { aA.x, aA.y, aA.z, aA.w, aB.x, aB.y, aB.z, aB.w };
#pragma unroll
            for (int i = 0; i < 8; ++i) {
                unsigned long long ap = pk2(av[i], av[i]);
#pragma unroll
                for (int j = 0; j < 4; ++j) fma2(acc[i][j], ap, bp[j]);
            }
        }
        __syncthreads();
    }

    float bo[8];
#pragma unroll
    for (int j = 0; j < 4; ++j) {
        int cb = ((j >> 1) ? 64 : 0) + tx * 4 + (j & 1) * 2;
        bo[j * 2]     = __ldg(bout + vb + cb);
        bo[j * 2 + 1] = __ldg(bout + vb + cb + 1);
    }
#pragma unroll
    for (int i = 0; i < 8; ++i) {
        int row = rb + ((i < 4) ? (ty * 4 + i) : (64 + ty * 4 + i - 4));
        float* orow = out + (size_t)row * 32000 + vb;
#pragma unroll
        for (int j = 0; j < 4; ++j) {
            int cb = ((j >> 1) ? 64 : 0) + tx * 4 + (j & 1) * 2;
            float lo, hi; upk2(acc[i][j], lo, hi);
            *(float2*)(orow + cb) = make_float2(lo + bo[j * 2], hi + bo[j * 2 + 1]);
        }
    }
}

extern "C" void kernel_launch(void* const* d_in, const int* in_sizes, int n_in,
                              void* d_out, int out_size)
{
    (void)in_sizes; (void)n_in; (void)out_size;
    const int*   qids = (const int*)d_in[0];
    const int*   sids = (const int*)d_in[1];
    const float* encE = (const float*)d_in[2];
    const float* Wih0 = (const float*)d_in[3];
    const float* Whh0 = (const float*)d_in[4];
    const float* b0   = (const float*)d_in[5];
    const float* Wih1 = (const float*)d_in[6];
    const float* Whh1 = (const float*)d_in[7];
    const float* b1   = (const float*)d_in[8];
    const float* decE = (const float*)d_in[9];
    const float* dWih = (const float*)d_in[10];
    const float* dWhh = (const float*)d_in[11];
    const float* db   = (const float*)d_in[12];
    const float* Wout = (const float*)d_in[13];
    const float* bout = (const float*)d_in[14];
    float* out = (float*)d_out;

    k_tr<<<1280, 256>>>(Whh0, Wih1, Whh1, dWih, dWhh);
    k_pre<<<1312, 256>>>(qids, sids, encE, Wih0, b0, decE, dWih, db);
    k_enc<<<128, 512>>>(b1);
    k_dec<<<128, 512>>>();
    k_out<<<dim3(250, 25), 256>>>(Wout, bout, out);
}

// round 16
// speedup vs baseline: 1.5228x; 1.5228x over previous
#include <cuda_runtime.h>
#include <math.h>
#include <stdint.h>

// Scratch (device globals -- no runtime allocation allowed)
__device__ float g_X0[2048 * 1024];   // enc layer0 input gates  [s*32+b][j]
__device__ float g_Xd[3200 * 1024];   // dec input gates         [t*32+b][j]
__device__ float g_enc[32 * 64 * 256];// enc_out [b][s][h]
__device__ float g_htop[32 * 256];    // final top-layer h
__device__ float g_H2[3200 * 256];    // decoder hiddens [b*100+t][h]
// transposed weights [k][j] for broadcast-FMA GEMVs
__device__ float g_WT0[256 * 1024];   // Whh0^T
__device__ float g_WT1[512 * 1024];   // [Wih1 ; Whh1]^T
__device__ float g_WTd[512 * 1024];   // [dWih[:,128:384] ; dWhh]^T

__device__ __forceinline__ float sigf(float x) { return 1.f / (1.f + expf(-x)); }

__device__ __forceinline__ float wred(float v) {
#pragma unroll
    for (int o = 16; o; o >>= 1) v += __shfl_xor_sync(0xffffffffu, v, o);
    return v;
}

// DSMEM store: write v to the same smem offset in cluster CTA `rank`
__device__ __forceinline__ void stc(float* p, int rank, float v) {
    unsigned a = (unsigned)__cvta_generic_to_shared(p);
    unsigned r;
    asm volatile("mapa.shared::cluster.u32 %0, %1, %2;" : "=r"(r) : "r"(a), "r"(rank));
    asm volatile("st.shared::cluster.f32 [%0], %1;" :: "r"(r), "f"(v) : "memory");
}
__device__ __forceinline__ void csync() {
    asm volatile("barrier.cluster.arrive.aligned;" ::: "memory");
    asm volatile("barrier.cluster.wait.aligned;" ::: "memory");
}
__device__ __forceinline__ void carrive() {
    asm volatile("barrier.cluster.arrive.aligned;" ::: "memory");
}
__device__ __forceinline__ void cwait() {
    asm volatile("barrier.cluster.wait.aligned;" ::: "memory");
}

// packed f32x2 FMA (sm_100+ PTX)
__device__ __forceinline__ unsigned long long pk2(float lo, float hi) {
    unsigned long long r;
    asm("mov.b64 %0, {%1,%2};" : "=l"(r) : "f"(lo), "f"(hi));
    return r;
}
__device__ __forceinline__ void fma2(unsigned long long& d, unsigned long long a,
                                     unsigned long long b) {
    asm("fma.rn.f32x2 %0, %1, %2, %0;" : "+l"(d) : "l"(a), "l"(b));
}
__device__ __forceinline__ void upk2(unsigned long long v, float& lo, float& hi) {
    asm("mov.b64 {%0,%1}, %2;" : "=f"(lo), "=f"(hi) : "l"(v));
}

// ============================================================================
// k_tr: transpose recurrent weights into [k][j] layout (1280 rows of 1024)
// ============================================================================
__global__ void k_tr(const float* __restrict__ Whh0, const float* __restrict__ Wih1,
                     const float* __restrict__ Whh1, const float* __restrict__ dWih,
                     const float* __restrict__ dWhh)
{
    const int row = blockIdx.x;
    const int j0 = threadIdx.x * 4;
    const float* src; long stride; float* dst; int k;
    if (row < 256) {
        k = row; src = Whh0 + k; stride = 256; dst = g_WT0 + k * 1024;
    } else if (row < 768) {
        k = row - 256;
        src = (k < 256) ? (Wih1 + k) : (Whh1 + (k - 256));
        stride = 256; dst = g_WT1 + k * 1024;
    } else {
        k = row - 768;
        if (k < 256) { src = dWih + 128 + k; stride = 384; }
        else         { src = dWhh + (k - 256); stride = 256; }
        dst = g_WTd + k * 1024;
    }
    float4 v;
    v.x = __ldg(src + (long)(j0 + 0) * stride);
    v.y = __ldg(src + (long)(j0 + 1) * stride);
    v.z = __ldg(src + (long)(j0 + 2) * stride);
    v.w = __ldg(src + (long)(j0 + 3) * stride);
    *(float4*)(dst + j0) = v;
}

// ============================================================================
// k_pre: X0[r][j] = b0[j] + emb(q)[r].Wih0[j]; Xd[r][j] = db[j] + emb(d)[r].dWih[j][0:128]
// ============================================================================
__global__ void k_pre(const int* __restrict__ qids, const int* __restrict__ sids,
                      const float* __restrict__ encE, const float* __restrict__ Wih0,
                      const float* __restrict__ b0, const float* __restrict__ decE,
                      const float* __restrict__ dWih, const float* __restrict__ db)
{
    __shared__ __align__(16) float4 a_s[16 * 32];
    const int blk = blockIdx.x, tid = threadIdx.x;
    const bool isX0 = blk < 512;
    const int u = isX0 ? blk : blk - 512;
    const int rt = u >> 2, jb = (u & 3) << 8;
    const float4* Ef = (const float4*)(isX0 ? encE : decE);
#pragma unroll
    for (int i = 0; i < 2; ++i) {
        int lin = tid + i * 256;
        int rr = lin >> 5, e4 = lin & 31;
        int row = rt * 16 + rr, b = row & 31, idx = row >> 5;
        int tok = isX0 ? qids[b * 64 + idx] : (idx == 0 ? 1 : sids[b * 100 + idx - 1]);
        a_s[rr * 32 + e4] = Ef[(size_t)tok * 32 + e4];
    }
    __syncthreads();
    const int j = jb + tid;
    const float4* Wf = (const float4*)(isX0 ? (Wih0 + j * 128) : (dWih + j * 384));
    float acc[16];
#pragma unroll
    for (int r = 0; r < 16; ++r) acc[r] = 0.f;
#pragma unroll 4
    for (int e4 = 0; e4 < 32; ++e4) {
        float4 w = __ldg(Wf + e4);
#pragma unroll
        for (int r = 0; r < 16; ++r) {
            float4 a = a_s[r * 32 + e4];
            acc[r] += a.x * w.x + a.y * w.y + a.z * w.z + a.w * w.w;
        }
    }
    const float bias = isX0 ? __ldg(b0 + j) : __ldg(db + j);
    float* dst = isX0 ? g_X0 : g_Xd;
#pragma unroll
    for (int r = 0; r < 16; ++r) dst[(rt * 16 + r) * 1024 + j] = bias + acc[r];
}

// ============================================================================
// Cluster-8 recurrence (R10 math) with split arrive/wait: the GEMV half that
// doesn't depend on the just-broadcast vector runs between arrive and wait.
// ============================================================================
__global__ void __launch_bounds__(512) __cluster_dims__(8, 1, 1)
k_enc(const float* __restrict__ b1)
{
    __shared__ __align__(16) float2 H0[2][256], H1[2][256];
    __shared__ __align__(16) float2 part[16][128];
    __shared__ __align__(16) float2 gt[128];
    const int cid = blockIdx.x >> 3, rank = blockIdx.x & 7;
    const int b0 = 2 * cid;
    const int tid = threadIdx.x;
    const int q = tid >> 5, cg = tid & 31;
    const int colf4 = (cg >> 3) * 64 + 8 * rank + (cg & 7);
    const int jg = (tid >> 5) * 256 + 32 * rank + (tid & 31);   // valid tid<128
    float c0 = 0.f, c1 = 0.f;
    float bias1 = (tid < 128) ? __ldg(b1 + jg) : 0.f;

    if (tid < 256) { H0[0][tid] = make_float2(0.f, 0.f); H1[0][tid] = make_float2(0.f, 0.f); }
    __syncthreads();

    for (int s = 0; s < 64; ++s) {
        const int p = s & 1;
        float xa = 0.f, xb = 0.f;
        if (tid < 128) {
            xa = __ldg(&g_X0[(s * 32 + b0) * 1024 + jg]);
            xb = __ldg(&g_X0[(s * 32 + b0 + 1) * 1024 + jg]);
        }
        // ---- L0 gates: K=256, 16 k per slice ----
        {
            const unsigned long long* hv = (const unsigned long long*)&H0[p][16 * q];
            const float4* wp = (const float4*)g_WT0 + (16 * q) * 256 + colf4;
            unsigned long long a0 = 0, a1 = 0, a2 = 0, a3 = 0;
#pragma unroll
            for (int k = 0; k < 16; ++k) {
                unsigned long long hp = hv[k];
                float4 w = __ldg(wp); wp += 256;
                fma2(a0, hp, pk2(w.x, w.x));
                fma2(a1, hp, pk2(w.y, w.y));
                fma2(a2, hp, pk2(w.z, w.z));
                fma2(a3, hp, pk2(w.w, w.w));
            }
            unsigned long long* pr = (unsigned long long*)&part[q][cg * 4];
            pr[0] = a0; pr[1] = a1; pr[2] = a2; pr[3] = a3;
        }
        __syncthreads();
        if (tid < 128) {
            float sx = xa, sy = xb;
#pragma unroll
            for (int qq = 0; qq < 16; ++qq) { float2 v = part[qq][tid]; sx += v.x; sy += v.y; }
            gt[tid] = make_float2(sx, sy);
        }
        __syncthreads();
        if (tid < 64) {
            int bh = tid >> 5, un = tid & 31;
            float gi_ = bh ? gt[un].y : gt[un].x;
            float gf_ = bh ? gt[32 + un].y : gt[32 + un].x;
            float gg_ = bh ? gt[64 + un].y : gt[64 + un].x;
            float go_ = bh ? gt[96 + un].y : gt[96 + un].x;
            c0 = sigf(gf_) * c0 + sigf(gi_) * tanhf(gg_);
            float hn = sigf(go_) * tanhf(c0);
            float* dst = ((float*)&H0[p ^ 1][32 * rank + un]) + bh;
#pragma unroll
            for (int r = 0; r < 8; ++r) stc(dst, r, hn);
        }
        carrive();
        // ---- L1 gates, H1_prev half (q>=8): independent of the broadcast ----
        if (q >= 8) {
            const unsigned long long* hv = (const unsigned long long*)&H1[p][32 * (q - 8)];
            const float4* wp = (const float4*)g_WT1 + (32 * q) * 256 + colf4;
            unsigned long long a0 = 0, a1 = 0, a2 = 0, a3 = 0;
#pragma unroll
            for (int k = 0; k < 32; ++k) {
                unsigned long long hp = hv[k];
                float4 w = __ldg(wp); wp += 256;
                fma2(a0, hp, pk2(w.x, w.x));
                fma2(a1, hp, pk2(w.y, w.y));
                fma2(a2, hp, pk2(w.z, w.z));
                fma2(a3, hp, pk2(w.w, w.w));
            }
            unsigned long long* pr = (unsigned long long*)&part[q][cg * 4];
            pr[0] = a0; pr[1] = a1; pr[2] = a2; pr[3] = a3;
        }
        cwait();
        // ---- L1 gates, H0_new half (q<8) ----
        if (q < 8) {
            const unsigned long long* hv = (const unsigned long long*)&H0[p ^ 1][32 * q];
            const float4* wp = (const float4*)g_WT1 + (32 * q) * 256 + colf4;
            unsigned long long a0 = 0, a1 = 0, a2 = 0, a3 = 0;
#pragma unroll
            for (int k = 0; k < 32; ++k) {
                unsigned long long hp = hv[k];
                float4 w = __ldg(wp); wp += 256;
                fma2(a0, hp, pk2(w.x, w.x));
                fma2(a1, hp, pk2(w.y, w.y));
                fma2(a2, hp, pk2(w.z, w.z));
                fma2(a3, hp, pk2(w.w, w.w));
            }
            unsigned long long* pr = (unsigned long long*)&part[q][cg * 4];
            pr[0] = a0; pr[1] = a1; pr[2] = a2; pr[3] = a3;
        }
        __syncthreads();
        if (tid < 128) {
            float sx = bias1, sy = bias1;
#pragma unroll
            for (int qq = 0; qq < 16; ++qq) { float2 v = part[qq][tid]; sx += v.x; sy += v.y; }
            gt[tid] = make_float2(sx, sy);
        }
        __syncthreads();
        if (tid < 64) {
            int bh = tid >> 5, un = tid & 31;
            float gi_ = bh ? gt[un].y : gt[un].x;
            float gf_ = bh ? gt[32 + un].y : gt[32 + un].x;
            float gg_ = bh ? gt[64 + un].y : gt[64 + un].x;
            float go_ = bh ? gt[96 + un].y : gt[96 + un].x;
            c1 = sigf(gf_) * c1 + sigf(gi_) * tanhf(gg_);
            float hn = sigf(go_) * tanhf(c1);
            float* dst = ((float*)&H1[p ^ 1][32 * rank + un]) + bh;
#pragma unroll
            for (int r = 0; r < 8; ++r) stc(dst, r, hn);
            g_enc[((b0 + bh) * 64 + s) * 256 + 32 * rank + un] = hn;
            if (s == 63) g_htop[(b0 + bh) * 256 + 32 * rank + un] = hn;
        }
        csync();
    }
}

__global__ void __launch_bounds__(512) __cluster_dims__(8, 1, 1)
k_dec()
{
    __shared__ __align__(16) float2 Hd[2][256], Ctx[256];
    __shared__ __align__(16) float2 part[16][128];
    __shared__ __align__(16) float2 gt[128];
    __shared__ float sc[2][64];
    __shared__ float rz[2];
    const int cid = blockIdx.x >> 3, rank = blockIdx.x & 7;
    const int b0 = 2 * cid;
    const int tid = threadIdx.x;
    const int q = tid >> 5, cg = tid & 31;
    const int colf4 = (cg >> 3) * 64 + 8 * rank + (cg & 7);
    const int jg = (tid >> 5) * 256 + 32 * rank + (tid & 31);

    if (tid < 256)
        Hd[0][tid] = make_float2(g_htop[b0 * 256 + tid], g_htop[(b0 + 1) * 256 + tid]);
    __syncthreads();

    for (int t = 0; t < 100; ++t) {
        const int p = t & 1;
        float xa = 0.f, xb = 0.f;
        if (tid < 128) {
            xa = __ldg(&g_Xd[(t * 32 + b0) * 1024 + jg]);
            xb = __ldg(&g_Xd[(t * 32 + b0 + 1) * 1024 + jg]);
        }
        // ---- scores: rank owns s in [8*rank, 8*rank+8); warp per (bh, sl) ----
        {
            int bh = tid >> 8;
            int sl = (tid >> 5) & 7;
            int l = tid & 31;
            int s = 8 * rank + sl;
            const float4* er = (const float4*)(g_enc + ((b0 + bh) * 64 + s) * 256) + l * 2;
            float4 e0 = __ldg(er), e1 = __ldg(er + 1);
            const float2* hp = &Hd[p][l * 8];
            float h0_ = bh ? hp[0].y : hp[0].x, h1_ = bh ? hp[1].y : hp[1].x;
            float h2_ = bh ? hp[2].y : hp[2].x, h3_ = bh ? hp[3].y : hp[3].x;
            float h4_ = bh ? hp[4].y : hp[4].x, h5_ = bh ? hp[5].y : hp[5].x;
            float h6_ = bh ? hp[6].y : hp[6].x, h7_ = bh ? hp[7].y : hp[7].x;
            float pr = e0.x * h0_ + e0.y * h1_ + e0.z * h2_ + e0.w * h3_
                     + e1.x * h4_ + e1.y * h5_ + e1.z * h6_ + e1.w * h7_;
            pr = wred(pr);
            if (l == 0) {
#pragma unroll
                for (int r = 0; r < 8; ++r) stc(&sc[bh][s], r, pr);
            }
        }
        carrive();
        // ---- gates, Hd half (q>=8): independent of the scores broadcast ----
        if (q >= 8) {
            const unsigned long long* hv = (const unsigned long long*)&Hd[p][32 * (q - 8)];
            const float4* wp = (const float4*)g_WTd + (32 * q) * 256 + colf4;
            unsigned long long a0 = 0, a1 = 0, a2 = 0, a3 = 0;
#pragma unroll
            for (int k = 0; k < 32; ++k) {
                unsigned long long hp = hv[k];
                float4 w = __ldg(wp); wp += 256;
                fma2(a0, hp, pk2(w.x, w.x));
                fma2(a1, hp, pk2(w.y, w.y));
                fma2(a2, hp, pk2(w.z, w.z));
                fma2(a3, hp, pk2(w.w, w.w));
            }
            unsigned long long* pr = (unsigned long long*)&part[q][cg * 4];
            pr[0] = a0; pr[1] = a1; pr[2] = a2; pr[3] = a3;
        }
        cwait();
        // ---- softmax (replicated per CTA) ----
        if (tid < 64) {
            int bh = tid >> 5, l = tid & 31;
            float s0 = sc[bh][l], s1 = sc[bh][l + 32];
            float m = fmaxf(s0, s1);
#pragma unroll
            for (int o = 16; o; o >>= 1) m = fmaxf(m, __shfl_xor_sync(0xffffffffu, m, o));
            float e0 = expf(s0 - m), e1 = expf(s1 - m);
            sc[bh][l] = e0; sc[bh][l + 32] = e1;
            float ssum = wred(e0 + e1);
            if (l == 0) rz[bh] = 1.f / ssum;
        }
        __syncthreads();
        // ---- ctx: rank owns k-slice [32*rank, 32*rank+32) ----
        if (tid < 64) {
            int bh = tid >> 5, kl = tid & 31;
            const float* base = g_enc + ((b0 + bh) * 64) * 256 + 32 * rank + kl;
            float a = 0.f;
#pragma unroll 8
            for (int s = 0; s < 64; ++s) a += sc[bh][s] * __ldg(base + s * 256);
            float val = a * rz[bh];
            float* dst = ((float*)&Ctx[32 * rank + kl]) + bh;
#pragma unroll
            for (int r = 0; r < 8; ++r) stc(dst, r, val);
        }
        csync();
        // ---- gates, Ctx half (q<8) ----
        if (q < 8) {
            const unsigned long long* hv = (const unsigned long long*)&Ctx[32 * q];
            const float4* wp = (const float4*)g_WTd + (32 * q) * 256 + colf4;
            unsigned long long a0 = 0, a1 = 0, a2 = 0, a3 = 0;
#pragma unroll
            for (int k = 0; k < 32; ++k) {
                unsigned long long hp = hv[k];
                float4 w = __ldg(wp); wp += 256;
                fma2(a0, hp, pk2(w.x, w.x));
                fma2(a1, hp, pk2(w.y, w.y));
                fma2(a2, hp, pk2(w.z, w.z));
                fma2(a3, hp, pk2(w.w, w.w));
            }
            unsigned long long* pr = (unsigned long long*)&part[q][cg * 4];
            pr[0] = a0; pr[1] = a1; pr[2] = a2; pr[3] = a3;
        }
        __syncthreads();
        if (tid < 128) {
            float sx = xa, sy = xb;
#pragma unroll
            for (int qq = 0; qq < 16; ++qq) { float2 v = part[qq][tid]; sx += v.x; sy += v.y; }
            gt[tid] = make_float2(sx, sy);
        }
        __syncthreads();
        // ---- cell (c_in = 0): h2 = sig(o)*tanh(sig(i)*tanh(g)) ----
        if (tid < 64) {
            int bh = tid >> 5, un = tid & 31;
            float gi_ = bh ? gt[un].y : gt[un].x;
            float gg_ = bh ? gt[64 + un].y : gt[64 + un].x;
            float go_ = bh ? gt[96 + un].y : gt[96 + un].x;
            float h2 = sigf(go_) * tanhf(sigf(gi_) * tanhf(gg_));
            float* dst = ((float*)&Hd[p ^ 1][32 * rank + un]) + bh;
#pragma unroll
            for (int r = 0; r < 8; ++r) stc(dst, r, h2);
            g_H2[((b0 + bh) * 100 + t) * 256 + 32 * rank + un] = h2;
        }
        csync();
    }
}

// ============================================================================
// k_out: out[r][v] = H2[r].Wout[v] + bout[v]; 128x128x16 tiles, FFMA2 (proven)
// ============================================================================
__global__ void __launch_bounds__(256) k_out(const float* __restrict__ Wout,
                                             const float* __restrict__ bout,
                                             float* __restrict__ out)
{
    __shared__ __align__(16) float As[16][132], Bs[16][132];
    const int tid = threadIdx.x;
    const int rb = blockIdx.y * 128, vb = blockIdx.x * 128;
    const int tx = tid & 15, ty = tid >> 4;
    const int r0 = tid >> 2, k0 = (tid & 3) * 4;
    const int r1 = (tid + 256) >> 2, k1 = ((tid + 256) & 3) * 4;

    unsigned long long acc[8][4];
#pragma unroll
    for (int i = 0; i < 8; ++i)
#pragma unroll
        for (int j = 0; j < 4; ++j) acc[i][j] = 0ull;

    const float* A = g_H2;
    float4 a0 = *(const float4*)(A + (rb + r0) * 256 + k0);
    float4 a1 = *(const float4*)(A + (rb + r1) * 256 + k1);
    float4 bv0 = *(const float4*)(Wout + (size_t)(vb + r0) * 256 + k0);
    float4 bv1 = *(const float4*)(Wout + (size_t)(vb + r1) * 256 + k1);

    for (int kc = 0; kc < 16; ++kc) {
        As[k0 + 0][r0] = a0.x; As[k0 + 1][r0] = a0.y; As[k0 + 2][r0] = a0.z; As[k0 + 3][r0] = a0.w;
        As[k1 + 0][r1] = a1.x; As[k1 + 1][r1] = a1.y; As[k1 + 2][r1] = a1.z; As[k1 + 3][r1] = a1.w;
        Bs[k0 + 0][r0] = bv0.x; Bs[k0 + 1][r0] = bv0.y; Bs[k0 + 2][r0] = bv0.z; Bs[k0 + 3][r0] = bv0.w;
        Bs[k1 + 0][r1] = bv1.x; Bs[k1 + 1][r1] = bv1.y; Bs[k1 + 2][r1] = bv1.z; Bs[k1 + 3][r1] = bv1.w;
        __syncthreads();
        if (kc < 15) {
            int kb = (kc + 1) * 16;
            a0 = *(const float4*)(A + (rb + r0) * 256 + kb + k0);
            a1 = *(const float4*)(A + (rb + r1) * 256 + kb + k1);
            bv0 = *(const float4*)(Wout + (size_t)(vb + r0) * 256 + kb + k0);
            bv1 = *(const float4*)(Wout + (size_t)(vb + r1) * 256 + kb + k1);
        }
#pragma unroll
        for (int k = 0; k < 16; ++k) {
            float4 aA = *(const float4*)&As[k][ty * 4];
            float4 aB = *(const float4*)&As[k][ty * 4 + 64];
            float4 bA = *(const float4*)&Bs[k][tx * 4];
            float4 bB = *(const float4*)&Bs[k][tx * 4 + 64];
            unsigned long long bp[4] = { pk2(bA.x, bA.y), pk2(bA.z, bA.w),
                                         pk2(bB.x, bB.y), pk2(bB.z, bB.w) };
            float av[8] = { aA.x, aA.y, aA.z, aA.w, aB.x, aB.y, aB.z, aB.w };
#pragma unroll
            for (int i = 0; i < 8; ++i) {
                unsigned long long ap = pk2(av[i], av[i]);
#pragma unroll
                for (int j = 0; j < 4; ++j) fma2(acc[i][j], ap, bp[j]);
            }
        }
        __syncthreads();
    }

    float bo[8];
#pragma unroll
    for (int j = 0; j < 4; ++j) {
        int cb = ((j >> 1) ? 64 : 0) + tx * 4 + (j & 1) * 2;
        bo[j * 2]     = __ldg(bout + vb + cb);
        bo[j * 2 + 1] = __ldg(bout + vb + cb + 1);
    }
#pragma unroll
    for (int i = 0; i < 8; ++i) {
        int row = rb + ((i < 4) ? (ty * 4 + i) : (64 + ty * 4 + i - 4));
        float* orow = out + (size_t)row * 32000 + vb;
#pragma unroll
        for (int j = 0; j < 4; ++j) {
            int cb = ((j >> 1) ? 64 : 0) + tx * 4 + (j & 1) * 2;
            float lo, hi; upk2(acc[i][j], lo, hi);
            *(float2*)(orow + cb) = make_float2(lo + bo[j * 2], hi + bo[j * 2 + 1]);
        }
    }
}

extern "C" void kernel_launch(void* const* d_in, const int* in_sizes, int n_in,
                              void* d_out, int out_size)
{
    (void)in_sizes; (void)n_in; (void)out_size;
    const int*   qids = (const int*)d_in[0];
    const int*   sids = (const int*)d_in[1];
    const float* encE = (const float*)d_in[2];
    const float* Wih0 = (const float*)d_in[3];
    const float* Whh0 = (const float*)d_in[4];
    const float* b0   = (const float*)d_in[5];
    const float* Wih1 = (const float*)d_in[6];
    const float* Whh1 = (const float*)d_in[7];
    const float* b1   = (const float*)d_in[8];
    const float* decE = (const float*)d_in[9];
    const float* dWih = (const float*)d_in[10];
    const float* dWhh = (const float*)d_in[11];
    const float* db   = (const float*)d_in[12];
    const float* Wout = (const float*)d_in[13];
    const float* bout = (const float*)d_in[14];
    float* out = (float*)d_out;

    k_tr<<<1280, 256>>>(Whh0, Wih1, Whh1, dWih, dWhh);
    k_pre<<<1312, 256>>>(qids, sids, encE, Wih0, b0, decE, dWih, db);
    k_enc<<<128, 512>>>(b1);
    k_dec<<<128, 512>>>();
    k_out<<<dim3(250, 25), 256>>>(Wout, bout, out);
}

// round 17
// speedup vs baseline: 1.7465x; 1.1469x over previous
#include <cuda_runtime.h>
#include <math.h>
#include <stdint.h>

// Scratch (device globals -- no runtime allocation allowed)
__device__ float g_X0[2048 * 1024];   // enc layer0 input gates  [s*32+b][j]
__device__ float g_Xd[3200 * 1024];   // dec input gates         [t*32+b][j]
__device__ float g_enc[32 * 64 * 256];// enc_out [b][s][h]
__device__ float g_htop[32 * 256];    // final top-layer h
__device__ float g_H2[3200 * 256];    // decoder hiddens [t*32+b][h]  (t-major!)
// transposed weights [k][j] for broadcast-FMA GEMVs
__device__ float g_WT0[256 * 1024];   // Whh0^T
__device__ float g_WT1[512 * 1024];   // [Wih1 ; Whh1]^T
__device__ float g_WTd[512 * 1024];   // [dWih[:,128:384] ; dWhh]^T

__device__ __forceinline__ float sigf(float x) { return 1.f / (1.f + expf(-x)); }

__device__ __forceinline__ float wred(float v) {
#pragma unroll
    for (int o = 16; o; o >>= 1) v += __shfl_xor_sync(0xffffffffu, v, o);
    return v;
}

// DSMEM store: write v to the same smem offset in cluster CTA `rank`
__device__ __forceinline__ void stc(float* p, int rank, float v) {
    unsigned a = (unsigned)__cvta_generic_to_shared(p);
    unsigned r;
    asm volatile("mapa.shared::cluster.u32 %0, %1, %2;" : "=r"(r) : "r"(a), "r"(rank));
    asm volatile("st.shared::cluster.f32 [%0], %1;" :: "r"(r), "f"(v) : "memory");
}
__device__ __forceinline__ void csync() {
    asm volatile("barrier.cluster.arrive.aligned;" ::: "memory");
    asm volatile("barrier.cluster.wait.aligned;" ::: "memory");
}

// packed f32x2 FMA (sm_100+ PTX)
__device__ __forceinline__ unsigned long long pk2(float lo, float hi) {
    unsigned long long r;
    asm("mov.b64 %0, {%1,%2};" : "=l"(r) : "f"(lo), "f"(hi));
    return r;
}
__device__ __forceinline__ void fma2(unsigned long long& d, unsigned long long a,
                                     unsigned long long b) {
    asm("fma.rn.f32x2 %0, %1, %2, %0;" : "+l"(d) : "l"(a), "l"(b));
}
__device__ __forceinline__ void upk2(unsigned long long v, float& lo, float& hi) {
    asm("mov.b64 {%0,%1}, %2;" : "=f"(lo), "=f"(hi) : "l"(v));
}

// ============================================================================
// k_tr: transpose recurrent weights into [k][j] layout (1280 rows of 1024)
// ============================================================================
__global__ void k_tr(const float* __restrict__ Whh0, const float* __restrict__ Wih1,
                     const float* __restrict__ Whh1, const float* __restrict__ dWih,
                     const float* __restrict__ dWhh)
{
    const int row = blockIdx.x;
    const int j0 = threadIdx.x * 4;
    const float* src; long stride; float* dst; int k;
    if (row < 256) {
        k = row; src = Whh0 + k; stride = 256; dst = g_WT0 + k * 1024;
    } else if (row < 768) {
        k = row - 256;
        src = (k < 256) ? (Wih1 + k) : (Whh1 + (k - 256));
        stride = 256; dst = g_WT1 + k * 1024;
    } else {
        k = row - 768;
        if (k < 256) { src = dWih + 128 + k; stride = 384; }
        else         { src = dWhh + (k - 256); stride = 256; }
        dst = g_WTd + k * 1024;
    }
    float4 v;
    v.x = __ldg(src + (long)(j0 + 0) * stride);
    v.y = __ldg(src + (long)(j0 + 1) * stride);
    v.z = __ldg(src + (long)(j0 + 2) * stride);
    v.w = __ldg(src + (long)(j0 + 3) * stride);
    *(float4*)(dst + j0) = v;
}

// ============================================================================
// k_pre: X0[r][j] = b0[j] + emb(q)[r].Wih0[j]; Xd[r][j] = db[j] + emb(d)[r].dWih[j][0:128]
// ============================================================================
__global__ void k_pre(const int* __restrict__ qids, const int* __restrict__ sids,
                      const float* __restrict__ encE, const float* __restrict__ Wih0,
                      const float* __restrict__ b0, const float* __restrict__ decE,
                      const float* __restrict__ dWih, const float* __restrict__ db)
{
    __shared__ __align__(16) float4 a_s[16 * 32];
    const int blk = blockIdx.x, tid = threadIdx.x;
    const bool isX0 = blk < 512;
    const int u = isX0 ? blk : blk - 512;
    const int rt = u >> 2, jb = (u & 3) << 8;
    const float4* Ef = (const float4*)(isX0 ? encE : decE);
#pragma unroll
    for (int i = 0; i < 2; ++i) {
        int lin = tid + i * 256;
        int rr = lin >> 5, e4 = lin & 31;
        int row = rt * 16 + rr, b = row & 31, idx = row >> 5;
        int tok = isX0 ? qids[b * 64 + idx] : (idx == 0 ? 1 : sids[b * 100 + idx - 1]);
        a_s[rr * 32 + e4] = Ef[(size_t)tok * 32 + e4];
    }
    __syncthreads();
    const int j = jb + tid;
    const float4* Wf = (const float4*)(isX0 ? (Wih0 + j * 128) : (dWih + j * 384));
    float acc[16];
#pragma unroll
    for (int r = 0; r < 16; ++r) acc[r] = 0.f;
#pragma unroll 4
    for (int e4 = 0; e4 < 32; ++e4) {
        float4 w = __ldg(Wf + e4);
#pragma unroll
        for (int r = 0; r < 16; ++r) {
            float4 a = a_s[r * 32 + e4];
            acc[r] += a.x * w.x + a.y * w.y + a.z * w.z + a.w * w.w;
        }
    }
    const float bias = isX0 ? __ldg(b0 + j) : __ldg(db + j);
    float* dst = isX0 ? g_X0 : g_Xd;
#pragma unroll
    for (int r = 0; r < 16; ++r) dst[(rt * 16 + r) * 1024 + j] = bias + acc[r];
}

// ============================================================================
// Cluster-8 recurrence (R10 proven): 2 batch elems per cluster in f32x2 lanes;
// rank owns 32 hidden units.  k_enc identical to the 2494us winner.
// ============================================================================
__global__ void __launch_bounds__(512) __cluster_dims__(8, 1, 1)
k_enc(const float* __restrict__ b1)
{
    __shared__ __align__(16) float2 H0[2][256], H1[2][256];
    __shared__ __align__(16) float2 part[16][128];
    __shared__ __align__(16) float2 gt[128];
    const int cid = blockIdx.x >> 3, rank = blockIdx.x & 7;
    const int b0 = 2 * cid;
    const int tid = threadIdx.x;
    const int q = tid >> 5, cg = tid & 31;
    const int colf4 = (cg >> 3) * 64 + 8 * rank + (cg & 7);
    const int jg = (tid >> 5) * 256 + 32 * rank + (tid & 31);   // valid tid<128
    float c0 = 0.f, c1 = 0.f;
    float bias1 = (tid < 128) ? __ldg(b1 + jg) : 0.f;

    if (tid < 256) { H0[0][tid] = make_float2(0.f, 0.f); H1[0][tid] = make_float2(0.f, 0.f); }
    __syncthreads();

    for (int s = 0; s < 64; ++s) {
        const int p = s & 1;
        float xa = 0.f, xb = 0.f;
        if (tid < 128) {
            xa = __ldg(&g_X0[(s * 32 + b0) * 1024 + jg]);
            xb = __ldg(&g_X0[(s * 32 + b0 + 1) * 1024 + jg]);
        }
        {
            const unsigned long long* hv = (const unsigned long long*)&H0[p][16 * q];
            const float4* wp = (const float4*)g_WT0 + (16 * q) * 256 + colf4;
            unsigned long long a0 = 0, a1 = 0, a2 = 0, a3 = 0;
#pragma unroll
            for (int k = 0; k < 16; ++k) {
                unsigned long long hp = hv[k];
                float4 w = __ldg(wp); wp += 256;
                fma2(a0, hp, pk2(w.x, w.x));
                fma2(a1, hp, pk2(w.y, w.y));
                fma2(a2, hp, pk2(w.z, w.z));
                fma2(a3, hp, pk2(w.w, w.w));
            }
            unsigned long long* pr = (unsigned long long*)&part[q][cg * 4];
            pr[0] = a0; pr[1] = a1; pr[2] = a2; pr[3] = a3;
        }
        __syncthreads();
        if (tid < 128) {
            float sx = xa, sy = xb;
#pragma unroll
            for (int qq = 0; qq < 16; ++qq) { float2 v = part[qq][tid]; sx += v.x; sy += v.y; }
            gt[tid] = make_float2(sx, sy);
        }
        __syncthreads();
        if (tid < 64) {
            int bh = tid >> 5, un = tid & 31;
            float gi_ = bh ? gt[un].y : gt[un].x;
            float gf_ = bh ? gt[32 + un].y : gt[32 + un].x;
            float gg_ = bh ? gt[64 + un].y : gt[64 + un].x;
            float go_ = bh ? gt[96 + un].y : gt[96 + un].x;
            c0 = sigf(gf_) * c0 + sigf(gi_) * tanhf(gg_);
            float hn = sigf(go_) * tanhf(c0);
            float* dst = ((float*)&H0[p ^ 1][32 * rank + un]) + bh;
#pragma unroll
            for (int r = 0; r < 8; ++r) stc(dst, r, hn);
        }
        csync();
        {
            const unsigned long long* hv = (q < 8)
                ? (const unsigned long long*)&H0[p ^ 1][32 * q]
                : (const unsigned long long*)&H1[p][32 * (q - 8)];
            const float4* wp = (const float4*)g_WT1 + (32 * q) * 256 + colf4;
            unsigned long long a0 = 0, a1 = 0, a2 = 0, a3 = 0;
#pragma unroll
            for (int k = 0; k < 32; ++k) {
                unsigned long long hp = hv[k];
                float4 w = __ldg(wp); wp += 256;
                fma2(a0, hp, pk2(w.x, w.x));
                fma2(a1, hp, pk2(w.y, w.y));
                fma2(a2, hp, pk2(w.z, w.z));
                fma2(a3, hp, pk2(w.w, w.w));
            }
            unsigned long long* pr = (unsigned long long*)&part[q][cg * 4];
            pr[0] = a0; pr[1] = a1; pr[2] = a2; pr[3] = a3;
        }
        __syncthreads();
        if (tid < 128) {
            float sx = bias1, sy = bias1;
#pragma unroll
            for (int qq = 0; qq < 16; ++qq) { float2 v = part[qq][tid]; sx += v.x; sy += v.y; }
            gt[tid] = make_float2(sx, sy);
        }
        __syncthreads();
        if (tid < 64) {
            int bh = tid >> 5, un = tid & 31;
            float gi_ = bh ? gt[un].y : gt[un].x;
            float gf_ = bh ? gt[32 + un].y : gt[32 + un].x;
            float gg_ = bh ? gt[64 + un].y : gt[64 + un].x;
            float go_ = bh ? gt[96 + un].y : gt[96 + un].x;
            c1 = sigf(gf_) * c1 + sigf(gi_) * tanhf(gg_);
            float hn = sigf(go_) * tanhf(c1);
            float* dst = ((float*)&H1[p ^ 1][32 * rank + un]) + bh;
#pragma unroll
            for (int r = 0; r < 8; ++r) stc(dst, r, hn);
            g_enc[((b0 + bh) * 64 + s) * 256 + 32 * rank + un] = hn;
            if (s == 63) g_htop[(b0 + bh) * 256 + 32 * rank + un] = hn;
        }
        csync();
    }
}

// ============================================================================
// k_dec: R10 body, parameterized over [t0, t1).  State handoff through g_H2
// (t-major rows): t0>0 initializes Hd from row (t0-1)*32+b.
// ============================================================================
__global__ void __launch_bounds__(512) __cluster_dims__(8, 1, 1)
k_dec(int t0, int t1)
{
    __shared__ __align__(16) float2 Hd[2][256], Ctx[256];
    __shared__ __align__(16) float2 part[16][128];
    __shared__ __align__(16) float2 gt[128];
    __shared__ float sc[2][64];
    __shared__ float rz[2];
    const int cid = blockIdx.x >> 3, rank = blockIdx.x & 7;
    const int b0 = 2 * cid;
    const int tid = threadIdx.x;
    const int q = tid >> 5, cg = tid & 31;
    const int colf4 = (cg >> 3) * 64 + 8 * rank + (cg & 7);
    const int jg = (tid >> 5) * 256 + 32 * rank + (tid & 31);

    if (tid < 256) {
        if (t0 == 0)
            Hd[0][tid] = make_float2(g_htop[b0 * 256 + tid], g_htop[(b0 + 1) * 256 + tid]);
        else
            Hd[0][tid] = make_float2(g_H2[((t0 - 1) * 32 + b0) * 256 + tid],
                                     g_H2[((t0 - 1) * 32 + b0 + 1) * 256 + tid]);
    }
    __syncthreads();

    for (int t = t0; t < t1; ++t) {
        const int p = (t - t0) & 1;
        float xa = 0.f, xb = 0.f;
        if (tid < 128) {
            xa = __ldg(&g_Xd[(t * 32 + b0) * 1024 + jg]);
            xb = __ldg(&g_Xd[(t * 32 + b0 + 1) * 1024 + jg]);
        }
        // ---- scores: rank owns s in [8*rank, 8*rank+8); warp per (bh, sl) ----
        {
            int bh = tid >> 8;
            int sl = (tid >> 5) & 7;
            int l = tid & 31;
            int s = 8 * rank + sl;
            const float4* er = (const float4*)(g_enc + ((b0 + bh) * 64 + s) * 256) + l * 2;
            float4 e0 = __ldg(er), e1 = __ldg(er + 1);
            const float2* hp = &Hd[p][l * 8];
            float h0_ = bh ? hp[0].y : hp[0].x, h1_ = bh ? hp[1].y : hp[1].x;
            float h2_ = bh ? hp[2].y : hp[2].x, h3_ = bh ? hp[3].y : hp[3].x;
            float h4_ = bh ? hp[4].y : hp[4].x, h5_ = bh ? hp[5].y : hp[5].x;
            float h6_ = bh ? hp[6].y : hp[6].x, h7_ = bh ? hp[7].y : hp[7].x;
            float pr = e0.x * h0_ + e0.y * h1_ + e0.z * h2_ + e0.w * h3_
                     + e1.x * h4_ + e1.y * h5_ + e1.z * h6_ + e1.w * h7_;
            pr = wred(pr);
            if (l == 0) {
#pragma unroll
                for (int r = 0; r < 8; ++r) stc(&sc[bh][s], r, pr);
            }
        }
        csync();
        // ---- softmax (replicated per CTA) ----
        if (tid < 64) {
            int bh = tid >> 5, l = tid & 31;
            float s0 = sc[bh][l], s1 = sc[bh][l + 32];
            float m = fmaxf(s0, s1);
#pragma unroll
            for (int o = 16; o; o >>= 1) m = fmaxf(m, __shfl_xor_sync(0xffffffffu, m, o));
            float e0 = expf(s0 - m), e1 = expf(s1 - m);
            sc[bh][l] = e0; sc[bh][l + 32] = e1;
            float ssum = wred(e0 + e1);
            if (l == 0) rz[bh] = 1.f / ssum;
        }
        __syncthreads();
        // ---- ctx: rank owns k-slice [32*rank, 32*rank+32) ----
        if (tid < 64) {
            int bh = tid >> 5, kl = tid & 31;
            const float* base = g_enc + ((b0 + bh) * 64) * 256 + 32 * rank + kl;
            float a = 0.f;
#pragma unroll 8
            for (int s = 0; s < 64; ++s) a += sc[bh][s] * __ldg(base + s * 256);
            float val = a * rz[bh];
            float* dst = ((float*)&Ctx[32 * rank + kl]) + bh;
#pragma unroll
            for (int r = 0; r < 8; ++r) stc(dst, r, val);
        }
        csync();
        // ---- gates: K=512 = [Ctx ; Hd[p]], 32 k per slice ----
        {
            const unsigned long long* hv = (q < 8)
                ? (const unsigned long long*)&Ctx[32 * q]
                : (const unsigned long long*)&Hd[p][32 * (q - 8)];
            const float4* wp = (const float4*)g_WTd + (32 * q) * 256 + colf4;
            unsigned long long a0 = 0, a1 = 0, a2 = 0, a3 = 0;
#pragma unroll
            for (int k = 0; k < 32; ++k) {
                unsigned long long hp = hv[k];
                float4 w = __ldg(wp); wp += 256;
                fma2(a0, hp, pk2(w.x, w.x));
                fma2(a1, hp, pk2(w.y, w.y));
                fma2(a2, hp, pk2(w.z, w.z));
                fma2(a3, hp, pk2(w.w, w.w));
            }
            unsigned long long* pr = (unsigned long long*)&part[q][cg * 4];
            pr[0] = a0; pr[1] = a1; pr[2] = a2; pr[3] = a3;
        }
        __syncthreads();
        if (tid < 128) {
            float sx = xa, sy = xb;
#pragma unroll
            for (int qq = 0; qq < 16; ++qq) { float2 v = part[qq][tid]; sx += v.x; sy += v.y; }
            gt[tid] = make_float2(sx, sy);
        }
        __syncthreads();
        // ---- cell (c_in = 0): h2 = sig(o)*tanh(sig(i)*tanh(g)) ----
        if (tid < 64) {
            int bh = tid >> 5, un = tid & 31;
            float gi_ = bh ? gt[un].y : gt[un].x;
            float gg_ = bh ? gt[64 + un].y : gt[64 + un].x;
            float go_ = bh ? gt[96 + un].y : gt[96 + un].x;
            float h2 = sigf(go_) * tanhf(sigf(gi_) * tanhf(gg_));
            float* dst = ((float*)&Hd[p ^ 1][32 * rank + un]) + bh;
#pragma unroll
            for (int r = 0; r < 8; ++r) stc(dst, r, h2);
            g_H2[(t * 32 + (b0 + bh)) * 256 + 32 * rank + un] = h2;   // t-major
        }
        csync();
    }
}

// ============================================================================
// k_out: out = H2 @ Wout^T + bout; 128x128x16 tiles, FFMA2 (proven).
// H2 rows are t-major (r = t*32+b); epilogue maps to out row b*100+t.
// rbase selects the row-tile window so a prefix can launch early.
// ============================================================================
__global__ void __launch_bounds__(256) k_out(const float* __restrict__ Wout,
                                             const float* __restrict__ bout,
                                             float* __restrict__ out, int rbase)
{
    __shared__ __align__(16) float As[16][132], Bs[16][132];
    const int tid = threadIdx.x;
    const int rb = (rbase + blockIdx.y) * 128, vb = blockIdx.x * 128;
    const int tx = tid & 15, ty = tid >> 4;
    const int r0 = tid >> 2, k0 = (tid & 3) * 4;
    const int r1 = (tid + 256) >> 2, k1 = ((tid + 256) & 3) * 4;

    unsigned long long acc[8][4];
#pragma unroll
    for (int i = 0; i < 8; ++i)
#pragma unroll
        for (int j = 0; j < 4; ++j) acc[i][j] = 0ull;

    const float* A = g_H2;
    float4 a0 = *(const float4*)(A + (rb + r0) * 256 + k0);
    float4 a1 = *(const float4*)(A + (rb + r1) * 256 + k1);
    float4 bv0 = *(const float4*)(Wout + (size_t)(vb + r0) * 256 + k0);
    float4 bv1 = *(const float4*)(Wout + (size_t)(vb + r1) * 256 + k1);

    for (int kc = 0; kc < 16; ++kc) {
        As[k0 + 0][r0] = a0.x; As[k0 + 1][r0] = a0.y; As[k0 + 2][r0] = a0.z; As[k0 + 3][r0] = a0.w;
        As[k1 + 0][r1] = a1.x; As[k1 + 1][r1] = a1.y; As[k1 + 2][r1] = a1.z; As[k1 + 3][r1] = a1.w;
        Bs[k0 + 0][r0] = bv0.x; Bs[k0 + 1][r0] = bv0.y; Bs[k0 + 2][r0] = bv0.z; Bs[k0 + 3][r0] = bv0.w;
        Bs[k1 + 0][r1] = bv1.x; Bs[k1 + 1][r1] = bv1.y; Bs[k1 + 2][r1] = bv1.z; Bs[k1 + 3][r1] = bv1.w;
        __syncthreads();
        if (kc < 15) {
            int kb = (kc + 1) * 16;
            a0 = *(const float4*)(A + (rb + r0) * 256 + kb + k0);
            a1 = *(const float4*)(A + (rb + r1) * 256 + kb + k1);
            bv0 = *(const float4*)(Wout + (size_t)(vb + r0) * 256 + kb + k0);
            bv1 = *(const float4*)(Wout + (size_t)(vb + r1) * 256 + kb + k1);
        }
#pragma unroll
        for (int k = 0; k < 16; ++k) {
            float4 aA = *(const float4*)&As[k][ty * 4];
            float4 aB = *(const float4*)&As[k][ty * 4 + 64];
            float4 bA = *(const float4*)&Bs[k][tx * 4];
            float4 bB = *(const float4*)&Bs[k][tx * 4 + 64];
            unsigned long long bp[4] = { pk2(bA.x, bA.y), pk2(bA.z, bA.w),
                                         pk2(bB.x, bB.y), pk2(bB.z, bB.w) };
            float av[8] = { aA.x, aA.y, aA.z, aA.w, aB.x, aB.y, aB.z, aB.w };
#pragma unroll
            for (int i = 0; i < 8; ++i) {
                unsigned long long ap = pk2(av[i], av[i]);
#pragma unroll
                for (int j = 0; j < 4; ++j) fma2(acc[i][j], ap, bp[j]);
            }
        }
        __syncthreads();
    }

    float bo[8];
#pragma unroll
    for (int j = 0; j < 4; ++j) {
        int cb = ((j >> 1) ? 64 : 0) + tx * 4 + (j & 1) * 2;
        bo[j * 2]     = __ldg(bout + vb + cb);
        bo[j * 2 + 1] = __ldg(bout + vb + cb + 1);
    }
#pragma unroll
    for (int i = 0; i < 8; ++i) {
        int row = rb + ((i < 4) ? (ty * 4 + i) : (64 + ty * 4 + i - 4));
        int orow_idx = (row & 31) * 100 + (row >> 5);   // b*100 + t
        float* orow = out + (size_t)orow_idx * 32000 + vb;
#pragma unroll
        for (int j = 0; j < 4; ++j) {
            int cb = ((j >> 1) ? 64 : 0) + tx * 4 + (j & 1) * 2;
            float lo, hi; upk2(acc[i][j], lo, hi);
            *(float2*)(orow + cb) = make_float2(lo + bo[j * 2], hi + bo[j * 2 + 1]);
        }
    }
}

extern "C" void kernel_launch(void* const* d_in, const int* in_sizes, int n_in,
                              void* d_out, int out_size)
{
    (void)in_sizes; (void)n_in; (void)out_size;
    const int*   qids = (const int*)d_in[0];
    const int*   sids = (const int*)d_in[1];
    const float* encE = (const float*)d_in[2];
    const float* Wih0 = (const float*)d_in[3];
    const float* Whh0 = (const float*)d_in[4];
    const float* b0   = (const float*)d_in[5];
    const float* Wih1 = (const float*)d_in[6];
    const float* Whh1 = (const float*)d_in[7];
    const float* b1   = (const float*)d_in[8];
    const float* decE = (const float*)d_in[9];
    const float* dWih = (const float*)d_in[10];
    const float* dWhh = (const float*)d_in[11];
    const float* db   = (const float*)d_in[12];
    const float* Wout = (const float*)d_in[13];
    const float* bout = (const float*)d_in[14];
    float* out = (float*)d_out;

    // One-time aux stream/events (created on the uncaptured correctness call;
    // identical launch sequence every call thereafter).
    static cudaStream_t s_aux = nullptr;
    static cudaEvent_t  s_e1 = nullptr, s_e2 = nullptr;
    static int s_ok = -1;
    if (s_ok < 0) {
        s_ok = (cudaStreamCreateWithFlags(&s_aux, cudaStreamNonBlocking) == cudaSuccess &&
                cudaEventCreateWithFlags(&s_e1, cudaEventDisableTiming) == cudaSuccess &&
                cudaEventCreateWithFlags(&s_e2, cudaEventDisableTiming) == cudaSuccess) ? 1 : 0;
    }

    k_tr<<<1280, 256>>>(Whh0, Wih1, Whh1, dWih, dWhh);
    k_pre<<<1312, 256>>>(qids, sids, encE, Wih0, b0, decE, dWih, db);
    k_enc<<<128, 512>>>(b1);

    if (s_ok == 1) {
        // dec split at t=56: rows [0,1792) of t-major g_H2 complete after part 1.
        k_dec<<<128, 512>>>(0, 56);
        cudaEventRecord(s_e1, 0);
        k_dec<<<128, 512>>>(56, 100);                          // main stream
        cudaStreamWaitEvent(s_aux, s_e1, 0);
        k_out<<<dim3(250, 14), 256, 0, s_aux>>>(Wout, bout, out, 0);   // overlaps dec2
        cudaEventRecord(s_e2, s_aux);
        k_out<<<dim3(250, 11), 256>>>(Wout, bout, out, 14);    // after dec2
        cudaStreamWaitEvent(0, s_e2, 0);                       // rejoin aux stream
    } else {
        k_dec<<<128, 512>>>(0, 100);
        k_out<<<dim3(250, 25), 256>>>(Wout, bout, out, 0);
    }
}